// round 13
// baseline (speedup 1.0000x reference)
#include <cuda_runtime.h>
#include <math.h>

#define KDIM 64
#define DEG 32
#define N0_MAX 65536

// hop-0 aggregate scratch: 65536 x 64 f32 = 16 MB (static __device__, no alloc)
__device__ float g_agg0[N0_MAX * KDIM];

// reduce across a 16-lane half-warp (xor 8,4,2,1)
__device__ __forceinline__ float half_sum(float v) {
#pragma unroll
    for (int o = 8; o > 0; o >>= 1) v += __shfl_xor_sync(0xffffffffu, v, o);
    return v;
}

// renorm scale: min(1, 1/max(sqrt(ss), 1e-12)) == ss > 1 ? rsqrt(ss) : 1
__device__ __forceinline__ float renorm_scale(float ss) {
    return (ss > 1.0f) ? rsqrtf(ss) : 1.0f;
}

// ============================ hop 0 ============================
// R8 winner verbatim (66.5us measured; at the random-gather DRAM roofline).
__global__ void __launch_bounds__(128) hop0_kernel(
    const float* __restrict__ entity_emb,
    const int* __restrict__ node_ids0,
    const int* __restrict__ nbr0,
    int n0)
{
    const int node = blockIdx.x * (blockDim.x >> 5) + (threadIdx.x >> 5);
    const int lane = threadIdx.x & 31;
    const int sub  = lane >> 4;
    const int sl   = lane & 15;
    if (node >= n0) return;

    const int myidx = __ldg(nbr0 + (size_t)node * DEG + lane);
    const int tid   = __ldg(node_ids0 + node);

    float4 e[16];
#pragma unroll
    for (int i = 0; i < 16; i++) {
        const int id = __shfl_sync(0xffffffffu, myidx, i + (sub << 4));
        e[i] = __ldg((const float4*)(entity_emb + (size_t)id * KDIM) + sl);
    }
    float4 t = __ldg((const float4*)(entity_emb + (size_t)tid * KDIM) + sl);

    float4 s = make_float4(0.f, 0.f, 0.f, 0.f);
    float4 q = make_float4(0.f, 0.f, 0.f, 0.f);
#pragma unroll
    for (int i = 0; i < 16; i++) {
        const float ss = half_sum(e[i].x * e[i].x + e[i].y * e[i].y +
                                  e[i].z * e[i].z + e[i].w * e[i].w);
        const float sc = renorm_scale(ss);
        const float ex = e[i].x * sc, ey = e[i].y * sc;
        const float ez = e[i].z * sc, ew = e[i].w * sc;
        s.x += ex; s.y += ey; s.z += ez; s.w += ew;
        q.x += ex * ex; q.y += ey * ey; q.z += ez * ez; q.w += ew * ew;
    }

    s.x += __shfl_xor_sync(0xffffffffu, s.x, 16);
    s.y += __shfl_xor_sync(0xffffffffu, s.y, 16);
    s.z += __shfl_xor_sync(0xffffffffu, s.z, 16);
    s.w += __shfl_xor_sync(0xffffffffu, s.w, 16);
    q.x += __shfl_xor_sync(0xffffffffu, q.x, 16);
    q.y += __shfl_xor_sync(0xffffffffu, q.y, 16);
    q.z += __shfl_xor_sync(0xffffffffu, q.z, 16);
    q.w += __shfl_xor_sync(0xffffffffu, q.w, 16);

    const float tsc = renorm_scale(half_sum(t.x * t.x + t.y * t.y +
                                            t.z * t.z + t.w * t.w));

    if (sub == 0) {
        float4 o;
        o.x = s.x * s.x - q.x + t.x * tsc;
        o.y = s.y * s.y - q.y + t.y * tsc;
        o.z = s.z * s.z - q.z + t.z * tsc;
        o.w = s.w * s.w - q.w + t.w * tsc;
        *((float4*)(g_agg0 + (size_t)node * KDIM) + sl) = o;
    }
}

// ============================ hop 1 ============================
// One block (128 thr, 4 warps) handles TWO batch rows (2b, 2b+1):
//  - warp w gathers 8 agg0 rows: 4 for row0 (idx lanes 0-7) + 4 for row1
//    (idx lanes 8-15), half-warp sub splits each row's 8 neighbors -> MLP 8.
//  - warp 2 prefetches both item rows, warp 3 both user rows (top of kernel,
//    overlapped with gathers).
//  - epilogues run IN PARALLEL: warp 0 finishes row0, warp 1 finishes row1.
__global__ void __launch_bounds__(128) hop1_kernel(
    const float* __restrict__ entity_emb,
    const float* __restrict__ user_emb,
    const int* __restrict__ u,
    const int* __restrict__ item_ids,
    const int* __restrict__ nbr1_idx,
    float* __restrict__ out,
    int B)
{
    __shared__ float4 sm_s[2][4][16];
    __shared__ float4 sm_q[2][4][16];
    __shared__ float4 sm_t[2][16];
    __shared__ float4 sm_u[2][16];

    const int r0   = blockIdx.x * 2;
    const int r1   = r0 + 1;
    const int w    = threadIdx.x >> 5;
    const int lane = threadIdx.x & 31;
    const int sub  = lane >> 4;
    const int sl   = lane & 15;
    if (r0 >= B) return;
    const bool has1 = (r1 < B);

    // top-of-kernel prefetch: warp 2 -> item rows, warp 3 -> user rows
    if (w == 2) {
        const int r = sub ? r1 : r0;
        if (r < B) {
            const int it = __ldg(item_ids + r);
            sm_t[sub][sl] = __ldg((const float4*)(entity_emb + (size_t)it * KDIM) + sl);
        }
    }
    if (w == 3) {
        const int r = sub ? r1 : r0;
        if (r < B) {
            const int uid = __ldg(u + r);
            sm_u[sub][sl] = __ldg((const float4*)(user_emb + (size_t)uid * KDIM) + sl);
        }
    }

    // indices: lanes 0-7 -> row0 neighbors [8w,8w+8); lanes 8-15 -> row1 same
    int myidx = 0;
    if (lane < 8)
        myidx = __ldg(nbr1_idx + (size_t)r0 * DEG + w * 8 + lane);
    else if (lane < 16 && has1)
        myidx = __ldg(nbr1_idx + (size_t)r1 * DEG + w * 8 + (lane - 8));

    // 8 gathers per warp: e0[0..3] row0, e1[0..3] row1
    float4 e0[4], e1[4];
#pragma unroll
    for (int i = 0; i < 4; i++) {
        const int id0 = __shfl_sync(0xffffffffu, myidx, (sub << 2) + i);
        e0[i] = *((const float4*)(g_agg0 + (size_t)id0 * KDIM) + sl);
    }
#pragma unroll
    for (int i = 0; i < 4; i++) {
        const int id1 = __shfl_sync(0xffffffffu, myidx, 8 + (sub << 2) + i);
        e1[i] = *((const float4*)(g_agg0 + (size_t)id1 * KDIM) + sl);
    }

    float4 s0 = make_float4(0.f, 0.f, 0.f, 0.f), q0 = s0;
    float4 s1 = s0, q1 = s0;
#pragma unroll
    for (int i = 0; i < 4; i++) {
        s0.x += e0[i].x; s0.y += e0[i].y; s0.z += e0[i].z; s0.w += e0[i].w;
        q0.x += e0[i].x * e0[i].x; q0.y += e0[i].y * e0[i].y;
        q0.z += e0[i].z * e0[i].z; q0.w += e0[i].w * e0[i].w;
        s1.x += e1[i].x; s1.y += e1[i].y; s1.z += e1[i].z; s1.w += e1[i].w;
        q1.x += e1[i].x * e1[i].x; q1.y += e1[i].y * e1[i].y;
        q1.z += e1[i].z * e1[i].z; q1.w += e1[i].w * e1[i].w;
    }

    // combine half-warps (same dims at lane ^ 16)
#pragma unroll
    for (int r = 0; r < 2; r++) {
        float4& s = r ? s1 : s0;
        float4& q = r ? q1 : q0;
        s.x += __shfl_xor_sync(0xffffffffu, s.x, 16);
        s.y += __shfl_xor_sync(0xffffffffu, s.y, 16);
        s.z += __shfl_xor_sync(0xffffffffu, s.z, 16);
        s.w += __shfl_xor_sync(0xffffffffu, s.w, 16);
        q.x += __shfl_xor_sync(0xffffffffu, q.x, 16);
        q.y += __shfl_xor_sync(0xffffffffu, q.y, 16);
        q.z += __shfl_xor_sync(0xffffffffu, q.z, 16);
        q.w += __shfl_xor_sync(0xffffffffu, q.w, 16);
    }

    if (sub == 0) {
        sm_s[0][w][sl] = s0; sm_q[0][w][sl] = q0;
        sm_s[1][w][sl] = s1; sm_q[1][w][sl] = q1;
    }
    __syncthreads();

    // parallel epilogues: warp 0 -> row0, warp 1 -> row1
    if (w < 2) {
        const int r = w ? r1 : r0;
        if (w == 0 || has1) {
            float4 S = sm_s[w][0][sl], Q = sm_q[w][0][sl];
#pragma unroll
            for (int j = 1; j < 4; j++) {
                const float4 a = sm_s[w][j][sl], c = sm_q[w][j][sl];
                S.x += a.x; S.y += a.y; S.z += a.z; S.w += a.w;
                Q.x += c.x; Q.y += c.y; Q.z += c.z; Q.w += c.w;
            }

            const float4 t   = sm_t[w][sl];
            const float4 usr = sm_u[w][sl];

            const float tsc = renorm_scale(half_sum(t.x * t.x + t.y * t.y +
                                                    t.z * t.z + t.w * t.w));
            float4 items;
            items.x = S.x * S.x - Q.x + t.x * tsc;
            items.y = S.y * S.y - Q.y + t.y * tsc;
            items.z = S.z * S.z - Q.z + t.z * tsc;
            items.w = S.w * S.w - Q.w + t.w * tsc;

            const float usc = renorm_scale(half_sum(usr.x * usr.x + usr.y * usr.y +
                                                    usr.z * usr.z + usr.w * usr.w));
            const float dot = half_sum((usr.x * items.x + usr.y * items.y +
                                        usr.z * items.z + usr.w * items.w) * usc);
            if (lane == 0) out[r] = 1.0f / (1.0f + expf(-dot));
        }
    }
}

extern "C" void kernel_launch(void* const* d_in, const int* in_sizes, int n_in,
                              void* d_out, int out_size)
{
    const float* entity_emb = (const float*)d_in[0];
    const float* user_emb   = (const float*)d_in[1];
    // d_in[2..5] = Wa, ba, Wh, bh : dead code (softmax over singleton axis == 1)
    const int* u         = (const int*)d_in[6];
    const int* item_ids  = (const int*)d_in[7];
    const int* nbr1_idx  = (const int*)d_in[8];
    const int* node_ids0 = (const int*)d_in[9];
    const int* nbr0      = (const int*)d_in[10];

    const int B  = in_sizes[6];   // 2048
    const int n0 = in_sizes[9];   // 65536

    // hop 0: one warp per node, 4 warps per block
    {
        const int wpb = 4;
        const int blocks = (n0 + wpb - 1) / wpb;
        hop0_kernel<<<blocks, wpb * 32>>>(entity_emb, node_ids0, nbr0, n0);
    }
    // hop 1: one block (4 warps) per TWO batch rows
    hop1_kernel<<<(B + 1) / 2, 128>>>(entity_emb, user_emb, u, item_ids,
                                      nbr1_idx, (float*)d_out, B);
}

// round 14
// speedup vs baseline: 1.0304x; 1.0304x over previous
#include <cuda_runtime.h>
#include <math.h>

#define KDIM 64
#define DEG 32
#define N0_MAX 65536

// hop-0 aggregate scratch: 65536 x 64 f32 = 16 MB (static __device__, no alloc)
__device__ float g_agg0[N0_MAX * KDIM];

// reduce across a 16-lane half-warp (xor 8,4,2,1)
__device__ __forceinline__ float half_sum(float v) {
#pragma unroll
    for (int o = 8; o > 0; o >>= 1) v += __shfl_xor_sync(0xffffffffu, v, o);
    return v;
}

// renorm scale: min(1, 1/max(sqrt(ss), 1e-12)) == ss > 1 ? rsqrt(ss) : 1
__device__ __forceinline__ float renorm_scale(float ss) {
    return (ss > 1.0f) ? rsqrtf(ss) : 1.0f;
}

// ============================ hop 0 ============================
// R8 winner verbatim (66.5us; LTS-capped at ~8TB/s of L2 gather traffic).
__global__ void __launch_bounds__(128) hop0_kernel(
    const float* __restrict__ entity_emb,
    const int* __restrict__ node_ids0,
    const int* __restrict__ nbr0,
    int n0)
{
    const int node = blockIdx.x * (blockDim.x >> 5) + (threadIdx.x >> 5);
    const int lane = threadIdx.x & 31;
    const int sub  = lane >> 4;
    const int sl   = lane & 15;
    if (node >= n0) return;

    const int myidx = __ldg(nbr0 + (size_t)node * DEG + lane);
    const int tid   = __ldg(node_ids0 + node);

    float4 e[16];
#pragma unroll
    for (int i = 0; i < 16; i++) {
        const int id = __shfl_sync(0xffffffffu, myidx, i + (sub << 4));
        e[i] = __ldg((const float4*)(entity_emb + (size_t)id * KDIM) + sl);
    }
    float4 t = __ldg((const float4*)(entity_emb + (size_t)tid * KDIM) + sl);

    float4 s = make_float4(0.f, 0.f, 0.f, 0.f);
    float4 q = make_float4(0.f, 0.f, 0.f, 0.f);
#pragma unroll
    for (int i = 0; i < 16; i++) {
        const float ss = half_sum(e[i].x * e[i].x + e[i].y * e[i].y +
                                  e[i].z * e[i].z + e[i].w * e[i].w);
        const float sc = renorm_scale(ss);
        const float ex = e[i].x * sc, ey = e[i].y * sc;
        const float ez = e[i].z * sc, ew = e[i].w * sc;
        s.x += ex; s.y += ey; s.z += ez; s.w += ew;
        q.x += ex * ex; q.y += ey * ey; q.z += ez * ez; q.w += ew * ew;
    }

    s.x += __shfl_xor_sync(0xffffffffu, s.x, 16);
    s.y += __shfl_xor_sync(0xffffffffu, s.y, 16);
    s.z += __shfl_xor_sync(0xffffffffu, s.z, 16);
    s.w += __shfl_xor_sync(0xffffffffu, s.w, 16);
    q.x += __shfl_xor_sync(0xffffffffu, q.x, 16);
    q.y += __shfl_xor_sync(0xffffffffu, q.y, 16);
    q.z += __shfl_xor_sync(0xffffffffu, q.z, 16);
    q.w += __shfl_xor_sync(0xffffffffu, q.w, 16);

    const float tsc = renorm_scale(half_sum(t.x * t.x + t.y * t.y +
                                            t.z * t.z + t.w * t.w));

    if (sub == 0) {
        float4 o;
        o.x = s.x * s.x - q.x + t.x * tsc;
        o.y = s.y * s.y - q.y + t.y * tsc;
        o.z = s.z * s.z - q.z + t.z * tsc;
        o.w = s.w * s.w - q.w + t.w * tsc;
        *((float4*)(g_agg0 + (size_t)node * KDIM) + sl) = o;
    }
}

// ============================ hop 1 ============================
// R12 winner (7.52us): one block (4 warps) per row; warps 1 & 2 prefetch
// item/user rows into smem at the top; warp 0 epilogue reads smem only.
// R14 delta: agg0 gathers go through __ldg (read-only nc path) — safe since
// g_agg0 is written by the PREVIOUS kernel launch.
__global__ void __launch_bounds__(128) hop1_kernel(
    const float* __restrict__ entity_emb,
    const float* __restrict__ user_emb,
    const int* __restrict__ u,
    const int* __restrict__ item_ids,
    const int* __restrict__ nbr1_idx,
    float* __restrict__ out,
    int B)
{
    __shared__ float4 sm_s[4][16];
    __shared__ float4 sm_q[4][16];
    __shared__ float4 sm_t[16];
    __shared__ float4 sm_u[16];

    const int b    = blockIdx.x;
    const int w    = threadIdx.x >> 5;
    const int lane = threadIdx.x & 31;
    const int sub  = lane >> 4;
    const int sl   = lane & 15;
    if (b >= B) return;

    // top-of-kernel prefetch: warp 1 loads item row, warp 2 loads user row
    if (w == 1 && sub == 0) {
        const int it = __ldg(item_ids + b);
        sm_t[sl] = __ldg((const float4*)(entity_emb + (size_t)it * KDIM) + sl);
    }
    if (w == 2 && sub == 0) {
        const int uid = __ldg(u + b);
        sm_u[sl] = __ldg((const float4*)(user_emb + (size_t)uid * KDIM) + sl);
    }

    // lanes 0-7 hold this warp's 8 neighbor indices
    const int myidx = (lane < 8)
        ? __ldg(nbr1_idx + (size_t)b * DEG + w * 8 + lane) : 0;

    float4 e[4];
#pragma unroll
    for (int i = 0; i < 4; i++) {
        const int id = __shfl_sync(0xffffffffu, myidx, (sub << 2) + i);
        e[i] = __ldg((const float4*)(g_agg0 + (size_t)id * KDIM) + sl);
    }

    float4 s = make_float4(0.f, 0.f, 0.f, 0.f);
    float4 q = make_float4(0.f, 0.f, 0.f, 0.f);
#pragma unroll
    for (int i = 0; i < 4; i++) {
        s.x += e[i].x; s.y += e[i].y; s.z += e[i].z; s.w += e[i].w;
        q.x += e[i].x * e[i].x; q.y += e[i].y * e[i].y;
        q.z += e[i].z * e[i].z; q.w += e[i].w * e[i].w;
    }

    s.x += __shfl_xor_sync(0xffffffffu, s.x, 16);
    s.y += __shfl_xor_sync(0xffffffffu, s.y, 16);
    s.z += __shfl_xor_sync(0xffffffffu, s.z, 16);
    s.w += __shfl_xor_sync(0xffffffffu, s.w, 16);
    q.x += __shfl_xor_sync(0xffffffffu, q.x, 16);
    q.y += __shfl_xor_sync(0xffffffffu, q.y, 16);
    q.z += __shfl_xor_sync(0xffffffffu, q.z, 16);
    q.w += __shfl_xor_sync(0xffffffffu, q.w, 16);

    if (sub == 0) { sm_s[w][sl] = s; sm_q[w][sl] = q; }
    __syncthreads();

    if (w == 0) {
        float4 S = sm_s[0][sl], Q = sm_q[0][sl];
#pragma unroll
        for (int j = 1; j < 4; j++) {
            const float4 a = sm_s[j][sl], c = sm_q[j][sl];
            S.x += a.x; S.y += a.y; S.z += a.z; S.w += a.w;
            Q.x += c.x; Q.y += c.y; Q.z += c.z; Q.w += c.w;
        }

        const float4 t   = sm_t[sl];
        const float4 usr = sm_u[sl];

        const float tsc = renorm_scale(half_sum(t.x * t.x + t.y * t.y +
                                                t.z * t.z + t.w * t.w));
        float4 items;
        items.x = S.x * S.x - Q.x + t.x * tsc;
        items.y = S.y * S.y - Q.y + t.y * tsc;
        items.z = S.z * S.z - Q.z + t.z * tsc;
        items.w = S.w * S.w - Q.w + t.w * tsc;

        const float usc = renorm_scale(half_sum(usr.x * usr.x + usr.y * usr.y +
                                                usr.z * usr.z + usr.w * usr.w));
        const float dot = half_sum((usr.x * items.x + usr.y * items.y +
                                    usr.z * items.z + usr.w * items.w) * usc);
        if (lane == 0) out[b] = 1.0f / (1.0f + expf(-dot));
    }
}

extern "C" void kernel_launch(void* const* d_in, const int* in_sizes, int n_in,
                              void* d_out, int out_size)
{
    const float* entity_emb = (const float*)d_in[0];
    const float* user_emb   = (const float*)d_in[1];
    // d_in[2..5] = Wa, ba, Wh, bh : dead code (softmax over singleton axis == 1)
    const int* u         = (const int*)d_in[6];
    const int* item_ids  = (const int*)d_in[7];
    const int* nbr1_idx  = (const int*)d_in[8];
    const int* node_ids0 = (const int*)d_in[9];
    const int* nbr0      = (const int*)d_in[10];

    const int B  = in_sizes[6];   // 2048
    const int n0 = in_sizes[9];   // 65536

    // hop 0: one warp per node, 4 warps per block
    {
        const int wpb = 4;
        const int blocks = (n0 + wpb - 1) / wpb;
        hop0_kernel<<<blocks, wpb * 32>>>(entity_emb, node_ids0, nbr0, n0);
    }
    // hop 1: one block (4 warps) per batch row
    hop1_kernel<<<B, 128>>>(entity_emb, user_emb, u, item_ids, nbr1_idx,
                            (float*)d_out, B);
}